// round 7
// baseline (speedup 1.0000x reference)
#include <cuda_runtime.h>

// Problem constants (from reference): N=1048576 rows, H=128, B=1024 segments.
#define H_DIM 128
#define EPS 1e-12f

// Single fused kernel: 8 rows per warp; each 4-lane group owns one row.
// Lane g in a group holds float4 columns {g, g+4, ..., g+28} of its row.
// The 8 streaming e-loads are issued FIRST (MLP_p1 = 8, ~600cyc DRAM);
// the 10-probe binary search (L1-resident ptr, ~350cyc chain) and the
// d-broadcast loads execute entirely under that latency.
__global__ void __launch_bounds__(256, 4) sim_kernel(
    const float* __restrict__ emb,
    const float* __restrict__ summary,
    const int*   __restrict__ ptr,      // int32 (JAX x64 disabled)
    const float* __restrict__ dvec,
    const float* __restrict__ scale,
    float* __restrict__ out,
    int n_rows, int n_seg)
{
    const int wid  = (blockIdx.x * blockDim.x + threadIdx.x) >> 5;
    const int lane = threadIdx.x & 31;
    const int g    = lane & 3;        // position within 4-lane row group
    const int rsub = lane >> 2;       // which of the warp's 8 rows

    int row = wid * 8 + rsub;
    const bool valid = row < n_rows;
    row = min(row, n_rows - 1);

    const float4* e4 = reinterpret_cast<const float4*>(emb) + (size_t)row * (H_DIM / 4);

    // ---- all streaming loads front-batched (issued before anything else) ----
    float4 e[8];
    #pragma unroll
    for (int i = 0; i < 8; i++)
        e[i] = __ldcs(&e4[i * 4 + g]);

    // ---- segment binary search: seg = first s with ptr[s+1] > row.
    // ptr is 4KB, L1-resident; this dependent chain hides under the e-loads.
    int lo = 0, hi = n_seg;
    while (lo < hi) {
        int mid = (lo + hi) >> 1;
        if (__ldg(&ptr[mid + 1]) > row) hi = mid; else lo = mid + 1;
    }

    const float sc = __ldg(scale);
    const float4* d4 = reinterpret_cast<const float4*>(dvec);
    const float4* s4 = reinterpret_cast<const float4*>(summary) + (size_t)lo * (H_DIM / 4);

    // Self-dot (norm) from raw e — consumes the loads as they land.
    float ds = 0.0f;
    #pragma unroll
    for (int i = 0; i < 8; i++) {
        ds = fmaf(e[i].x, e[i].x, ds);
        ds = fmaf(e[i].y, e[i].y, ds);
        ds = fmaf(e[i].z, e[i].z, ds);
        ds = fmaf(e[i].w, e[i].w, ds);
    }

    // Fold d into e in place (register-neutral); d loads are broadcast L1 hits.
    #pragma unroll
    for (int i = 0; i < 8; i++) {
        const float4 d = __ldg(&d4[i * 4 + g]);
        e[i].x *= d.x; e[i].y *= d.y; e[i].z *= d.z; e[i].w *= d.w;
    }

    // Weighted dot with summary[seg] — L1/L2 hits, consumed immediately.
    float dw = 0.0f;
    #pragma unroll
    for (int i = 0; i < 8; i++) {
        const float4 s = __ldg(&s4[i * 4 + g]);
        dw = fmaf(e[i].x, s.x, dw);
        dw = fmaf(e[i].y, s.y, dw);
        dw = fmaf(e[i].z, s.z, dw);
        dw = fmaf(e[i].w, s.w, dw);
    }

    // Reduce within each 4-lane group (2 butterfly steps, both sums).
    #pragma unroll
    for (int off = 2; off > 0; off >>= 1) {
        ds += __shfl_xor_sync(0xFFFFFFFFu, ds, off);
        dw += __shfl_xor_sync(0xFFFFFFFFu, dw, off);
    }

    if (g == 0 && valid) {
        __stcs(&out[row], sc * __fdividef(dw, fmaxf(sqrtf(ds), EPS)));
    }
}

extern "C" void kernel_launch(void* const* d_in, const int* in_sizes, int n_in,
                              void* d_out, int out_size)
{
    const float* emb     = (const float*)d_in[0];   // [N, H]
    const float* summary = (const float*)d_in[1];   // [B, H]
    const int*   ptr     = (const int*)d_in[2];     // [B+1] int32
    const float* dvec    = (const float*)d_in[3];   // [H]
    const float* scale   = (const float*)d_in[4];   // [1]
    float*       out     = (float*)d_out;           // [N]

    const int n_rows = in_sizes[0] / H_DIM;   // N
    const int n_seg  = in_sizes[2] - 1;       // B

    // 8 rows per warp, 8 warps per block -> 64 rows per block.
    const int n_warps = (n_rows + 7) / 8;
    const int blocks  = (n_warps + 7) / 8;
    sim_kernel<<<blocks, 256>>>(emb, summary, ptr, dvec, scale, out, n_rows, n_seg);
}

// round 8
// speedup vs baseline: 1.2484x; 1.2484x over previous
#include <cuda_runtime.h>

// Problem constants (from reference): N=1048576 rows, H=128, B=1024 segments.
#define H_DIM 128
#define EPS 1e-12f
#define MAX_B 4096          // scratch sized generously vs B=1024
#define MAX_N (1 << 20)     // N = 1048576

// Precomputed w[s,h] = d[h] * summary[s,h]  (512KB for B=1024)
__device__ float g_wbuf[MAX_B * H_DIM];
// Precomputed row -> segment id (2MB for N=1M)
__device__ unsigned short g_seg[MAX_N];

// Fused prep: blocks [0, n_seg) fill the seg table (one block per segment),
// blocks [n_seg, n_seg + w_blocks) compute w = d (*) summary.
__global__ void __launch_bounds__(256) prep_kernel(
    const float* __restrict__ summary,
    const float* __restrict__ dvec,
    const int*   __restrict__ ptr,
    int n_rows, int n_seg, int w_total)
{
    const int b = blockIdx.x;
    if (b < n_seg) {
        const int start = ptr[b];
        const int end   = min(ptr[b + 1], n_rows);
        for (int i = start + (int)threadIdx.x; i < end; i += 256)
            g_seg[i] = (unsigned short)b;
    } else {
        const int i = (b - n_seg) * 256 + (int)threadIdx.x;
        if (i < w_total)
            g_wbuf[i] = summary[i] * dvec[i & (H_DIM - 1)];
    }
}

// 8 rows per warp; each 4-lane group owns one row.
// Lane g in a group holds float4 columns {g, g+4, ..., g+28} of its row.
// e-loads issued in two batches of 4 (MLP_p1 = 4) to keep live registers
// ~40 so 6 blocks/SM fit (48 warps, 75% occ) — latency hidden by warps
// instead of per-thread depth.
__global__ void __launch_bounds__(256, 6) sim_kernel(
    const float* __restrict__ emb,
    const float* __restrict__ scale,
    float* __restrict__ out,
    int n_rows)
{
    const int wid  = (blockIdx.x * blockDim.x + threadIdx.x) >> 5;
    const int lane = threadIdx.x & 31;
    const int g    = lane & 3;        // position within 4-lane row group
    const int rsub = lane >> 2;       // which of the warp's 8 rows

    int row = wid * 8 + rsub;
    const bool valid = row < n_rows;
    row = min(row, n_rows - 1);

    // ---- independent cached loads issued first ----
    const int   seg = (int)g_seg[row];
    const float sc  = __ldg(scale);

    const float4* e4 = reinterpret_cast<const float4*>(emb) + (size_t)row * (H_DIM / 4);
    const float4* w4 = reinterpret_cast<const float4*>(g_wbuf) + (size_t)seg * (H_DIM / 4);

    float ds = 0.0f;   // self-dot (norm)
    float dw = 0.0f;   // weighted dot

    // ---- first half: 4 streaming loads, then consume ----
    {
        float4 e0 = __ldcs(&e4[0 * 4 + g]);
        float4 e1 = __ldcs(&e4[1 * 4 + g]);
        float4 e2 = __ldcs(&e4[2 * 4 + g]);
        float4 e3 = __ldcs(&e4[3 * 4 + g]);

        ds = fmaf(e0.x, e0.x, ds); ds = fmaf(e0.y, e0.y, ds);
        ds = fmaf(e0.z, e0.z, ds); ds = fmaf(e0.w, e0.w, ds);
        ds = fmaf(e1.x, e1.x, ds); ds = fmaf(e1.y, e1.y, ds);
        ds = fmaf(e1.z, e1.z, ds); ds = fmaf(e1.w, e1.w, ds);
        ds = fmaf(e2.x, e2.x, ds); ds = fmaf(e2.y, e2.y, ds);
        ds = fmaf(e2.z, e2.z, ds); ds = fmaf(e2.w, e2.w, ds);
        ds = fmaf(e3.x, e3.x, ds); ds = fmaf(e3.y, e3.y, ds);
        ds = fmaf(e3.z, e3.z, ds); ds = fmaf(e3.w, e3.w, ds);

        const float4 w0 = __ldg(&w4[0 * 4 + g]);
        const float4 w1 = __ldg(&w4[1 * 4 + g]);
        const float4 w2 = __ldg(&w4[2 * 4 + g]);
        const float4 w3 = __ldg(&w4[3 * 4 + g]);
        dw = fmaf(e0.x, w0.x, dw); dw = fmaf(e0.y, w0.y, dw);
        dw = fmaf(e0.z, w0.z, dw); dw = fmaf(e0.w, w0.w, dw);
        dw = fmaf(e1.x, w1.x, dw); dw = fmaf(e1.y, w1.y, dw);
        dw = fmaf(e1.z, w1.z, dw); dw = fmaf(e1.w, w1.w, dw);
        dw = fmaf(e2.x, w2.x, dw); dw = fmaf(e2.y, w2.y, dw);
        dw = fmaf(e2.z, w2.z, dw); dw = fmaf(e2.w, w2.w, dw);
        dw = fmaf(e3.x, w3.x, dw); dw = fmaf(e3.y, w3.y, dw);
        dw = fmaf(e3.z, w3.z, dw); dw = fmaf(e3.w, w3.w, dw);
    }

    // ---- second half ----
    {
        float4 e0 = __ldcs(&e4[4 * 4 + g]);
        float4 e1 = __ldcs(&e4[5 * 4 + g]);
        float4 e2 = __ldcs(&e4[6 * 4 + g]);
        float4 e3 = __ldcs(&e4[7 * 4 + g]);

        ds = fmaf(e0.x, e0.x, ds); ds = fmaf(e0.y, e0.y, ds);
        ds = fmaf(e0.z, e0.z, ds); ds = fmaf(e0.w, e0.w, ds);
        ds = fmaf(e1.x, e1.x, ds); ds = fmaf(e1.y, e1.y, ds);
        ds = fmaf(e1.z, e1.z, ds); ds = fmaf(e1.w, e1.w, ds);
        ds = fmaf(e2.x, e2.x, ds); ds = fmaf(e2.y, e2.y, ds);
        ds = fmaf(e2.z, e2.z, ds); ds = fmaf(e2.w, e2.w, ds);
        ds = fmaf(e3.x, e3.x, ds); ds = fmaf(e3.y, e3.y, ds);
        ds = fmaf(e3.z, e3.z, ds); ds = fmaf(e3.w, e3.w, ds);

        const float4 w0 = __ldg(&w4[4 * 4 + g]);
        const float4 w1 = __ldg(&w4[5 * 4 + g]);
        const float4 w2 = __ldg(&w4[6 * 4 + g]);
        const float4 w3 = __ldg(&w4[7 * 4 + g]);
        dw = fmaf(e0.x, w0.x, dw); dw = fmaf(e0.y, w0.y, dw);
        dw = fmaf(e0.z, w0.z, dw); dw = fmaf(e0.w, w0.w, dw);
        dw = fmaf(e1.x, w1.x, dw); dw = fmaf(e1.y, w1.y, dw);
        dw = fmaf(e1.z, w1.z, dw); dw = fmaf(e1.w, w1.w, dw);
        dw = fmaf(e2.x, w2.x, dw); dw = fmaf(e2.y, w2.y, dw);
        dw = fmaf(e2.z, w2.z, dw); dw = fmaf(e2.w, w2.w, dw);
        dw = fmaf(e3.x, w3.x, dw); dw = fmaf(e3.y, w3.y, dw);
        dw = fmaf(e3.z, w3.z, dw); dw = fmaf(e3.w, w3.w, dw);
    }

    // Reduce within each 4-lane group (2 butterfly steps, both sums).
    #pragma unroll
    for (int off = 2; off > 0; off >>= 1) {
        ds += __shfl_xor_sync(0xFFFFFFFFu, ds, off);
        dw += __shfl_xor_sync(0xFFFFFFFFu, dw, off);
    }

    if (g == 0 && valid) {
        __stcs(&out[row], sc * __fdividef(dw, fmaxf(sqrtf(ds), EPS)));
    }
}

extern "C" void kernel_launch(void* const* d_in, const int* in_sizes, int n_in,
                              void* d_out, int out_size)
{
    const float* emb     = (const float*)d_in[0];   // [N, H]
    const float* summary = (const float*)d_in[1];   // [B, H]
    const int*   ptr     = (const int*)d_in[2];     // [B+1] int32
    const float* dvec    = (const float*)d_in[3];   // [H]
    const float* scale   = (const float*)d_in[4];   // [1]
    float*       out     = (float*)d_out;           // [N]

    const int n_rows  = in_sizes[0] / H_DIM;   // N
    const int n_seg   = in_sizes[2] - 1;       // B
    const int w_total = in_sizes[1];           // B*H

    const int w_blocks = (w_total + 255) / 256;
    prep_kernel<<<n_seg + w_blocks, 256>>>(summary, dvec, ptr, n_rows, n_seg, w_total);

    // 8 rows per warp, 8 warps per block -> 64 rows per block.
    const int n_warps = (n_rows + 7) / 8;
    const int blocks  = (n_warps + 7) / 8;
    sim_kernel<<<blocks, 256>>>(emb, scale, out, n_rows);
}